// round 2
// baseline (speedup 1.0000x reference)
#include <cuda_runtime.h>
#include <math.h>
#include <float.h>

#define Bn 32
#define Ln 512
#define Nn 1024
#define Dn 64
#define TK 20
#define NNODE 32768           // B*N = 32*1024 (== L*64)
#define BN_EPS 1e-5f

// ---------------- scratch (static device globals; no allocation) ----------------
__device__ float g_ps  [4*NNODE];     // partial sums  (l-split)
__device__ float g_psq [4*NNODE];     // partial sumsq
__device__ float g_scale[NNODE];      // rstd per (b,n)
__device__ float g_shift[NNODE];      // -mean*rstd
__device__ float g_h  [NNODE*Dn];     // GEMM output (8MB)
__device__ float g_cos[Nn*Nn];        // cosine matrix (4MB)
__device__ float g_nrm[Nn];
__device__ float g_ei [Nn];
__device__ float g_ej [Nn];
__device__ int   g_topk[Nn*TK];
__device__ float g_ai [NNODE];
__device__ float g_aj [NNODE];
__device__ float g_out[NNODE*Dn];     // aggregated (8MB)
__device__ float g_xg [NNODE*Dn];     // post-BN1*emb (8MB)
__device__ float g_p1 [256*2*Dn];     // BN1 block partials [256][128]
__device__ float g_p2 [512*2*Dn];     // BN2 block partials [512][128]
__device__ float g_bn1f[2*Dn];        // BN1 scale/shift
__device__ float g_bn2f[2*Dn];        // BN2 scale/shift

// ---------------- K1: per-(b,n) sum/sumsq over L (l-split, no atomics) ----------
__global__ __launch_bounds__(256) void k1_stats(const float* __restrict__ x) {
    int n  = blockIdx.x * 256 + threadIdx.x;   // grid.x = 4 -> n in [0,1024)
    int b  = blockIdx.y;                       // 32
    int lc = blockIdx.z;                       // 4 chunks of 128
    const float* p = x + (size_t)b * Ln * Nn + (size_t)lc * 128 * Nn + n;
    float s = 0.f, sq = 0.f;
#pragma unroll 8
    for (int l = 0; l < 128; l++) {
        float v = p[(size_t)l * Nn];
        s += v; sq += v * v;
    }
    int m = b * Nn + n;
    g_ps [lc * NNODE + m] = s;
    g_psq[lc * NNODE + m] = sq;
}

// ---------------- K1b: finalize scale/shift + write gt -------------------------
__global__ __launch_bounds__(256) void k1b_fin(const float* __restrict__ x,
                                               float* __restrict__ dout) {
    int m = blockIdx.x * 256 + threadIdx.x;    // 128 blocks -> 32768
    float s  = g_ps [m] + g_ps [NNODE + m] + g_ps [2*NNODE + m] + g_ps [3*NNODE + m];
    float sq = g_psq[m] + g_psq[NNODE + m] + g_psq[2*NNODE + m] + g_psq[3*NNODE + m];
    float mean = s * (1.f / 512.f);
    float var  = sq * (1.f / 512.f) - mean * mean;   // NO eps (matches reference)
    float rstd = 1.f / sqrtf(var);
    g_scale[m] = rstd;
    g_shift[m] = -mean * rstd;
    int b = m >> 10, n = m & 1023;
    float xl = x[(size_t)b * Ln * Nn + (size_t)(Ln - 1) * Nn + n];
    float gv = xl * rstd - mean * rstd;
    if (!isfinite(gv)) gv = 0.f;                     // nan_to_num
    dout[NNODE + m] = gv;                            // gt is second half of output
}

// ---------------- K2: h = x @ lin_W  (one block per l, 64x64x512 tile) ---------
__global__ __launch_bounds__(256) void k2_gemm(const float* __restrict__ x,
                                               const float* __restrict__ W) {
    int l = blockIdx.x;                        // 512
    int tid = threadIdx.x;
    if (l == Ln - 1) {                          // enc last timestep zeroed -> h rows = 0
        for (int a = tid; a < 64 * 64; a += 256)
            g_h[(size_t)l * 64 * 64 + a] = 0.f;
        return;
    }
    __shared__ __align__(16) float As[64][65];
    __shared__ __align__(16) float Bs[64][68];
    float acc[4][4] = {};
    int ty = tid >> 4, tx = tid & 15;
    for (int kt = 0; kt < 8; kt++) {
#pragma unroll
        for (int r = 0; r < 16; r++) {
            int a = tid + r * 256;
            int c = a >> 6, j = a & 63;
            int m = c * 512 + kt * 64 + j;
            int bb = m >> 10, nn = m & 1023;
            float v = x[(size_t)bb * (Ln * Nn) + (size_t)l * Nn + nn];
            v = v * g_scale[m] + g_shift[m];
            if (!isfinite(v)) v = 0.f;
            As[c][j] = v;
            Bs[c][j] = W[(kt * 64 + c) * 64 + j];
        }
        __syncthreads();
#pragma unroll 8
        for (int j = 0; j < 64; j++) {
            float av[4];
#pragma unroll
            for (int r = 0; r < 4; r++) av[r] = As[ty * 4 + r][j];
            float4 bq = *(const float4*)&Bs[j][tx * 4];
            float bv[4] = {bq.x, bq.y, bq.z, bq.w};
#pragma unroll
            for (int r = 0; r < 4; r++)
#pragma unroll
                for (int s2 = 0; s2 < 4; s2++)
                    acc[r][s2] = fmaf(av[r], bv[s2], acc[r][s2]);
        }
        __syncthreads();
    }
#pragma unroll
    for (int r = 0; r < 4; r++)
#pragma unroll
        for (int s2 = 0; s2 < 4; s2++)
            g_h[((size_t)l * 64 + ty * 4 + r) * 64 + tx * 4 + s2] = acc[r][s2];
}

// ---------------- K3a: emb norms + att_em dots (warp per n) --------------------
__global__ __launch_bounds__(256) void k3a_emb(const float* __restrict__ emb,
                                               const float* __restrict__ aei,
                                               const float* __restrict__ aej) {
    int w = (blockIdx.x * 256 + threadIdx.x) >> 5;  // 128 blocks -> 1024 warps
    int lane = threadIdx.x & 31;
    float e1 = emb[w * 64 + lane], e2 = emb[w * 64 + 32 + lane];
    float sq = e1 * e1 + e2 * e2;
    float di = e1 * aei[lane] + e2 * aei[lane + 32];
    float dj = e1 * aej[lane] + e2 * aej[lane + 32];
#pragma unroll
    for (int off = 16; off; off >>= 1) {
        sq += __shfl_xor_sync(0xffffffffu, sq, off);
        di += __shfl_xor_sync(0xffffffffu, di, off);
        dj += __shfl_xor_sync(0xffffffffu, dj, off);
    }
    if (lane == 0) { g_nrm[w] = sqrtf(sq); g_ei[w] = di; g_ej[w] = dj; }
}

// ---------------- K3b1: cosine matrix (64x64 tiles) ----------------------------
__global__ __launch_bounds__(256) void k3b1_cos(const float* __restrict__ emb) {
    __shared__ float Ae[64][65];
    __shared__ float Be[64][65];
    int tid = threadIdx.x;
    int by = blockIdx.y, bx = blockIdx.x;
#pragma unroll
    for (int r = 0; r < 16; r++) {
        int a = tid + r * 256;
        int row = a >> 6, col = a & 63;
        Ae[row][col] = emb[(by * 64 + row) * 64 + col];
        Be[row][col] = emb[(bx * 64 + row) * 64 + col];
    }
    __syncthreads();
    int ty = tid >> 4, tx = tid & 15;
    float acc[4][4] = {};
#pragma unroll 8
    for (int d = 0; d < 64; d++) {
        float av[4], bv[4];
#pragma unroll
        for (int r = 0; r < 4; r++) { av[r] = Ae[ty * 4 + r][d]; bv[r] = Be[tx * 4 + r][d]; }
#pragma unroll
        for (int r = 0; r < 4; r++)
#pragma unroll
            for (int s2 = 0; s2 < 4; s2++)
                acc[r][s2] = fmaf(av[r], bv[s2], acc[r][s2]);
    }
#pragma unroll
    for (int r = 0; r < 4; r++)
#pragma unroll
        for (int s2 = 0; s2 < 4; s2++) {
            int rg = by * 64 + ty * 4 + r, cg = bx * 64 + tx * 4 + s2;
            g_cos[rg * 1024 + cg] = acc[r][s2] / (g_nrm[rg] * g_nrm[cg]);
        }
}

// ---------------- K3b2: top-20 per row (JAX tie rule: value desc, index asc) ----
__global__ __launch_bounds__(256) void k3b2_topk() {
    int r = blockIdx.x;
    __shared__ float sc[1024];
    __shared__ float sv[256];
    __shared__ int   si[256];
    for (int c = threadIdx.x; c < 1024; c += 256) sc[c] = g_cos[r * 1024 + c];
    __syncthreads();
    for (int t = 0; t < TK; t++) {
        float bv = -FLT_MAX; int bi = 1 << 30;
        for (int c = threadIdx.x; c < 1024; c += 256) {
            float v = sc[c];
            if (v > bv || (v == bv && c < bi)) { bv = v; bi = c; }
        }
        sv[threadIdx.x] = bv; si[threadIdx.x] = bi;
        __syncthreads();
        for (int off = 128; off; off >>= 1) {
            if (threadIdx.x < off) {
                float ov = sv[threadIdx.x + off]; int oi = si[threadIdx.x + off];
                if (ov > sv[threadIdx.x] || (ov == sv[threadIdx.x] && oi < si[threadIdx.x])) {
                    sv[threadIdx.x] = ov; si[threadIdx.x] = oi;
                }
            }
            __syncthreads();
        }
        if (threadIdx.x == 0) { g_topk[r * TK + t] = si[0]; sc[si[0]] = -FLT_MAX; }
        __syncthreads();
    }
}

// ---------------- K3c: a_i/a_j per node (warp per node) ------------------------
__global__ __launch_bounds__(256) void k3c_att(const float* __restrict__ ati,
                                               const float* __restrict__ atj) {
    int w = threadIdx.x >> 5, lane = threadIdx.x & 31;
    int v = blockIdx.x * 8 + w;                 // 4096 blocks
    float h1 = g_h[(size_t)v * 64 + lane], h2 = g_h[(size_t)v * 64 + 32 + lane];
    float di = h1 * ati[lane] + h2 * ati[lane + 32];
    float dj = h1 * atj[lane] + h2 * atj[lane + 32];
#pragma unroll
    for (int off = 16; off; off >>= 1) {
        di += __shfl_xor_sync(0xffffffffu, di, off);
        dj += __shfl_xor_sync(0xffffffffu, dj, off);
    }
    if (lane == 0) { g_ai[v] = di; g_aj[v] = dj; }
}

// ---------------- K4: per-node attention softmax + aggregation -----------------
__global__ __launch_bounds__(256) void k4_agg(const float* __restrict__ gnnb) {
    int grp = threadIdx.x >> 6;                 // 4 dst nodes / block
    int t   = threadIdx.x & 63;
    int v = blockIdx.x * 4 + grp;               // 8192 blocks
    int b = v >> 10, n = v & 1023;
    __shared__ float s_al[4][21];
    __shared__ int   s_sr[4][21];
    if (t < 32) {
        int k = t;
        bool active = (k <= 20);
        bool masked = false;
        int srcv = v;
        float lg = -FLT_MAX;
        if (active) {
            int s;
            if (k < 20) { s = g_topk[n * TK + k]; masked = (s == n); }
            else        { s = n; }                          // appended self-loop
            srcv = b * Nn + s;
            float L0 = g_ai[v] + g_ei[n] + g_aj[srcv] + g_ej[s];
            L0 = (L0 >= 0.f) ? L0 : 0.2f * L0;              // LeakyReLU(0.2)
            lg = masked ? -FLT_MAX : L0;                    // self-edge -> -inf
        }
        float m = lg;
#pragma unroll
        for (int off = 16; off; off >>= 1) m = fmaxf(m, __shfl_xor_sync(0xffffffffu, m, off));
        float e = (active && !masked) ? expf(lg - m) : 0.f;
        float den = e;
#pragma unroll
        for (int off = 16; off; off >>= 1) den += __shfl_xor_sync(0xffffffffu, den, off);
        if (active) { s_al[grp][k] = e / den; s_sr[grp][k] = srcv; }
    }
    __syncthreads();
    float acc = gnnb[t];
#pragma unroll
    for (int k = 0; k < 21; k++)
        acc += s_al[grp][k] * g_h[(size_t)s_sr[grp][k] * Dn + t];
    g_out[(size_t)v * Dn + t] = acc;
}

// ---------------- K5: BN1 block partials ---------------------------------------
__global__ __launch_bounds__(256) void k5_bn1p() {
    int r0 = blockIdx.x * 128;                  // 256 blocks
    int d = threadIdx.x & 63, rr = threadIdx.x >> 6;
    float s = 0.f, sq = 0.f;
    for (int r = r0 + rr; r < r0 + 128; r += 4) {
        float x = g_out[(size_t)r * 64 + d];
        s += x; sq += x * x;
    }
    __shared__ float rs[256], rq[256];
    rs[threadIdx.x] = s; rq[threadIdx.x] = sq;
    __syncthreads();
    if (threadIdx.x < 64) {
        int i = threadIdx.x;
        g_p1[blockIdx.x * 128 + i]      = rs[i] + rs[i + 64] + rs[i + 128] + rs[i + 192];
        g_p1[blockIdx.x * 128 + 64 + i] = rq[i] + rq[i + 64] + rq[i + 128] + rq[i + 192];
    }
}

__global__ void k5b_bn1f(const float* __restrict__ g1v, const float* __restrict__ b1v) {
    int d = threadIdx.x;                        // 64 threads
    float s = 0.f, sq = 0.f;
    for (int p = 0; p < 256; p++) { s += g_p1[p * 128 + d]; sq += g_p1[p * 128 + 64 + d]; }
    float mean = s / (float)NNODE;
    float var = sq / (float)NNODE - mean * mean;
    float rstd = 1.f / sqrtf(var + BN_EPS);
    float sA = rstd * g1v[d];
    g_bn1f[d] = sA; g_bn1f[64 + d] = b1v[d] - mean * sA;
}

// ---------------- K6: apply BN1 + relu + *emb -> xg; BN2 partials ---------------
__global__ __launch_bounds__(256) void k6_xg(const float* __restrict__ emb) {
    int d = threadIdx.x & 63;
    float sA = g_bn1f[d], sB = g_bn1f[64 + d];
    float s = 0.f, sq = 0.f;
    for (size_t e = blockIdx.x * 256 + threadIdx.x; e < (size_t)NNODE * 64; e += 512 * 256) {
        float x = g_out[e];
        float val = fmaxf(fmaf(x, sA, sB), 0.f);
        float xg = val * emb[(((int)(e >> 6)) & 1023) * 64 + d];
        g_xg[e] = xg;
        s += xg; sq += xg * xg;
    }
    __shared__ float rs[256], rq[256];
    rs[threadIdx.x] = s; rq[threadIdx.x] = sq;
    __syncthreads();
    if (threadIdx.x < 64) {
        int i = threadIdx.x;
        g_p2[blockIdx.x * 128 + i]      = rs[i] + rs[i + 64] + rs[i + 128] + rs[i + 192];
        g_p2[blockIdx.x * 128 + 64 + i] = rq[i] + rq[i + 64] + rq[i + 128] + rq[i + 192];
    }
}

__global__ void k6b_bn2f(const float* __restrict__ g2v, const float* __restrict__ b2v) {
    int d = threadIdx.x;
    float s = 0.f, sq = 0.f;
    for (int p = 0; p < 512; p++) { s += g_p2[p * 128 + d]; sq += g_p2[p * 128 + 64 + d]; }
    float mean = s / (float)NNODE;
    float var = sq / (float)NNODE - mean * mean;
    float rstd = 1.f / sqrtf(var + BN_EPS);
    float sA = rstd * g2v[d];
    g_bn2f[d] = sA; g_bn2f[64 + d] = b2v[d] - mean * sA;
}

// ---------------- K7: apply BN2 + relu + projection -> o ------------------------
__global__ __launch_bounds__(256) void k7_proj(const float* __restrict__ outW,
                                               const float* __restrict__ outb,
                                               float* __restrict__ dout) {
    int w = threadIdx.x >> 5, lane = threadIdx.x & 31;
    int v = blockIdx.x * 8 + w;                 // 4096 blocks
    int d1 = lane, d2 = lane + 32;
    float x1 = g_xg[(size_t)v * 64 + d1];
    float x2 = g_xg[(size_t)v * 64 + d2];
    float y = fmaxf(fmaf(x1, g_bn2f[d1], g_bn2f[64 + d1]), 0.f) * outW[d1]
            + fmaxf(fmaf(x2, g_bn2f[d2], g_bn2f[64 + d2]), 0.f) * outW[d2];
#pragma unroll
    for (int off = 16; off; off >>= 1) y += __shfl_xor_sync(0xffffffffu, y, off);
    if (lane == 0) dout[v] = y + outb[0];
}

// ---------------- launch --------------------------------------------------------
extern "C" void kernel_launch(void* const* d_in, const int* in_sizes, int n_in,
                              void* d_out, int out_size) {
    const float* x        = (const float*)d_in[0];
    const float* emb      = (const float*)d_in[1];
    const float* linW     = (const float*)d_in[2];
    const float* att_i    = (const float*)d_in[3];
    const float* att_j    = (const float*)d_in[4];
    const float* att_em_i = (const float*)d_in[5];
    const float* att_em_j = (const float*)d_in[6];
    const float* gnnb     = (const float*)d_in[7];
    const float* g1       = (const float*)d_in[8];
    const float* b1       = (const float*)d_in[9];
    const float* g2       = (const float*)d_in[10];
    const float* b2       = (const float*)d_in[11];
    const float* outW     = (const float*)d_in[12];
    const float* outb     = (const float*)d_in[13];
    float* out = (float*)d_out;

    k1_stats<<<dim3(4, 32, 4), 256>>>(x);
    k1b_fin <<<128, 256>>>(x, out);
    k2_gemm <<<512, 256>>>(x, linW);
    k3a_emb <<<128, 256>>>(emb, att_em_i, att_em_j);
    k3b1_cos<<<dim3(16, 16), 256>>>(emb);
    k3b2_topk<<<1024, 256>>>();
    k3c_att <<<4096, 256>>>(att_i, att_j);
    k4_agg  <<<8192, 256>>>(gnnb);
    k5_bn1p <<<256, 256>>>();
    k5b_bn1f<<<1, 64>>>(g1, b1);
    k6_xg   <<<512, 256>>>(emb);
    k6b_bn2f<<<1, 64>>>(g2, b2);
    k7_proj <<<4096, 256>>>(outW, outb, out);
}